// round 9
// baseline (speedup 1.0000x reference)
#include <cuda_runtime.h>
#include <cuda_bf16.h>
#include <math.h>
#include <stdint.h>

// Problem constants: B=64, LT=1024, LV=576, E=768, K=128
namespace cfg {
constexpr int Bn = 64;
constexpr int LT = 1024;
constexpr int LV = 576;
constexpr int E  = 768;
constexpr int Kd = 128;
}
using bf16 = __nv_bfloat16;

__device__ __forceinline__ void split2(float v, bf16& h, bf16& l) {
    h = __float2bfloat16(v);
    l = __float2bfloat16(v - __bfloat162float(h));
}

__device__ __forceinline__ uint32_t pack_bf2(bf16 a, bf16 b) {
    union { bf16 h[2]; uint32_t u; } w;
    w.h[0] = a; w.h[1] = b;
    return w.u;
}

__device__ __forceinline__ void mma16816(float* d, const uint32_t* a, const uint32_t* b) {
    asm volatile(
        "mma.sync.aligned.m16n8k16.row.col.f32.bf16.bf16.f32 "
        "{%0,%1,%2,%3}, {%4,%5,%6,%7}, {%8,%9}, {%0,%1,%2,%3};"
        : "+f"(d[0]), "+f"(d[1]), "+f"(d[2]), "+f"(d[3])
        : "r"(a[0]), "r"(a[1]), "r"(a[2]), "r"(a[3]), "r"(b[0]), "r"(b[1]));
}

__device__ __forceinline__ void ldm_x4(uint32_t* r, uint32_t saddr) {
    asm volatile("ldmatrix.sync.aligned.m8n8.x4.shared.b16 {%0,%1,%2,%3}, [%4];"
        : "=r"(r[0]), "=r"(r[1]), "=r"(r[2]), "=r"(r[3]) : "r"(saddr));
}
__device__ __forceinline__ void ldm_x4t(uint32_t* r, uint32_t saddr) {
    asm volatile("ldmatrix.sync.aligned.m8n8.x4.trans.shared.b16 {%0,%1,%2,%3}, [%4];"
        : "=r"(r[0]), "=r"(r[1]), "=r"(r[2]), "=r"(r[3]) : "r"(saddr));
}

__device__ __forceinline__ uint32_t smem_u32(const void* p) {
    uint32_t a;
    asm("{ .reg .u64 t; cvta.to.shared.u64 t, %1; cvt.u32.u64 %0, t; }"
        : "=r"(a) : "l"(p));
    return a;
}

#define CP_ASYNC16(s, g) \
    asm volatile("cp.async.cg.shared.global [%0], [%1], 16;" :: "r"(s), "l"(g))
#define CP_COMMIT() asm volatile("cp.async.commit_group;")
#define CP_WAIT1()  asm volatile("cp.async.wait_group 1;")
#define CP_WAIT0()  asm volatile("cp.async.wait_group 0;")

// Swizzles (conflict-free for their ldmatrix phases):
#define SWZ64(row, kb)  ((uint32_t)((row) * 64  + ((kb) ^ (((row) & 3) << 4))))
#define SWZ256(row, kb) ((uint32_t)((row) * 256 + ((kb) ^ (((row) & 7) << 4))))

// ===========================================================================
// Scratch (device globals; zero-initialized)
// ===========================================================================
#define DEV_BF16(name, n) __device__ __align__(256) bf16 name[n]
DEV_BF16(g_Thi,  64 * 1024 * 768);
DEV_BF16(g_Tlo,  64 * 1024 * 768);
DEV_BF16(g_Ihi,  64 * 576 * 768 + 64 * 768);   // +pad: GEMM5 reads 64 extra rows
DEV_BF16(g_Ilo,  64 * 576 * 768 + 64 * 768);
DEV_BF16(g_wbhi,  768 * 768);
DEV_BF16(g_wblo,  768 * 768);
DEV_BF16(g_wqhi,  768 * 128);
DEV_BF16(g_wqlo,  768 * 128);
DEV_BF16(g_wvhi,  768 * 128);
DEV_BF16(g_wvlo,  768 * 128);
DEV_BF16(g_wqqhi, 64 * 1024 * 128);
DEV_BF16(g_wqqlo, 64 * 1024 * 128);
DEV_BF16(g_wvvhi, 64 * 576 * 128);
DEV_BF16(g_wvvlo, 64 * 576 * 128);
DEV_BF16(g_A1hi,  64 * 768 * 128);
DEV_BF16(g_A1lo,  64 * 768 * 128);
DEV_BF16(g_M1hi,  64 * 768 * 128);
DEV_BF16(g_M1lo,  64 * 768 * 128);
DEV_BF16(g_A2hi,  64 * 768 * 128);
DEV_BF16(g_A2lo,  64 * 768 * 128);
DEV_BF16(g_Hhi,   64 * 768 * 128);
DEV_BF16(g_Hlo,   64 * 768 * 128);

__device__ float g_sv  [cfg::Bn * cfg::LV];
__device__ float g_sq  [cfg::Bn * cfg::LT];
__device__ float g_ctx [cfg::Bn * cfg::E];

// ===========================================================================
// Flat conversion: fp32 -> bf16 hi/lo
// ===========================================================================
__global__ void conv_flat(const float* __restrict__ X,
                          bf16* __restrict__ hi, bf16* __restrict__ lo, long n4)
{
    long idx = (long)blockIdx.x * blockDim.x + threadIdx.x;
    if (idx >= n4) return;
    float4 v = ((const float4*)X)[idx];
    union { bf16 h[4]; uint2 u; } H, L;
    split2(v.x, H.h[0], L.h[0]);
    split2(v.y, H.h[1], L.h[1]);
    split2(v.z, H.h[2], L.h[2]);
    split2(v.w, H.h[3], L.h[3]);
    ((uint2*)hi)[idx] = H.u;
    ((uint2*)lo)[idx] = L.u;
}

// ===========================================================================
// Merged-pair HMMA batched GEMM: C[M,128] = op(A)[M,K] @ B[K,128]
//   (fp32 via bf16x3 split; 3-stage cp.async; ldmatrix(.trans))
// Outputs: OUTHL hi/lo bf16 [M,128];
//          OUTS fused score: s[m] = sum_n tanh(Uhi+Ulo+C[m,n])*wh[n].
// ===========================================================================
constexpr int MATB   = 8192;
constexpr int STAGEB = 4 * MATB;
static constexpr int SMEM_MMA_BYTES = 3 * STAGEB;   // 98304 B

struct GArgs {
    const bf16 *Ahi, *Alo, *Bhi, *Blo;
    long sA, sB, sHL, sU, sS;
    bf16 *Chi, *Clo;
    const bf16 *Uhi, *Ulo;
    const float* wh;
    float* Sout;
    int Ktot, Mvalid, transA;
};

template <bool OUTHL, bool OUTS>
__global__ void __launch_bounds__(256, 2) mma_gemm(GArgs a0, GArgs a1, int splitX)
{
    extern __shared__ __align__(16) bf16 sm[];
    __shared__ float s_wh[128];
    const uint32_t smb = smem_u32(sm);

    const GArgs& A = (blockIdx.x < (unsigned)splitX) ? a0 : a1;
    const int bx = (blockIdx.x < (unsigned)splitX) ? blockIdx.x
                                                   : blockIdx.x - splitX;

    const int tid  = threadIdx.x;
    const int lane = tid & 31;
    const int wid  = tid >> 5;
    const int wm   = wid & 1;
    const int wn   = wid >> 1;
    const int g    = lane >> 2;
    const int t    = lane & 3;

    const long z    = blockIdx.z;
    const int  m0   = bx * 128;
    const int  Ktot = A.Ktot;
    const bool trA  = (A.transA != 0);

    if (OUTS && tid < 128) s_wh[tid] = A.wh[tid];

    const bf16* Ah = A.Ahi + z * A.sA + (trA ? 0 : (long)m0 * 768);
    const bf16* Al = A.Alo + z * A.sA + (trA ? 0 : (long)m0 * 768);
    const bf16* Bh = A.Bhi + z * A.sB;
    const bf16* Bl = A.Blo + z * A.sB;

    float acc[4][4][4];
#pragma unroll
    for (int i = 0; i < 4; i++)
#pragma unroll
        for (int j = 0; j < 4; j++)
#pragma unroll
            for (int q = 0; q < 4; q++) acc[i][j][q] = 0.f;

    const int nch = Ktot >> 5;

    const int nrow0 = (tid * 2)     >> 2, nc0 = ((tid * 2)     & 3) * 16;
    const int nrow1 = (tid * 2 + 1) >> 2, nc1 = ((tid * 2 + 1) & 3) * 16;
    const int trow0 = (tid * 2)     >> 4, tc0 = ((tid * 2)     & 15) * 16;
    const int trow1 = (tid * 2 + 1) >> 4, tc1 = ((tid * 2 + 1) & 15) * 16;

    auto load_chunk = [&](int c, int stage) {
        const int k0 = c << 5;
        const uint32_t sb = smb + stage * STAGEB;
        if (trA) {
            CP_ASYNC16(sb + SWZ256(trow0, tc0),
                       Ah + (long)(k0 + trow0) * 768 + m0 + tc0 / 2);
            CP_ASYNC16(sb + SWZ256(trow1, tc1),
                       Ah + (long)(k0 + trow1) * 768 + m0 + tc1 / 2);
            CP_ASYNC16(sb + MATB + SWZ256(trow0, tc0),
                       Al + (long)(k0 + trow0) * 768 + m0 + tc0 / 2);
            CP_ASYNC16(sb + MATB + SWZ256(trow1, tc1),
                       Al + (long)(k0 + trow1) * 768 + m0 + tc1 / 2);
        } else {
            CP_ASYNC16(sb + SWZ64(nrow0, nc0),
                       Ah + (long)nrow0 * 768 + k0 + nc0 / 2);
            CP_ASYNC16(sb + SWZ64(nrow1, nc1),
                       Ah + (long)nrow1 * 768 + k0 + nc1 / 2);
            CP_ASYNC16(sb + MATB + SWZ64(nrow0, nc0),
                       Al + (long)nrow0 * 768 + k0 + nc0 / 2);
            CP_ASYNC16(sb + MATB + SWZ64(nrow1, nc1),
                       Al + (long)nrow1 * 768 + k0 + nc1 / 2);
        }
        CP_ASYNC16(sb + 2 * MATB + SWZ256(trow0, tc0),
                   Bh + (long)(k0 + trow0) * 128 + tc0 / 2);
        CP_ASYNC16(sb + 2 * MATB + SWZ256(trow1, tc1),
                   Bh + (long)(k0 + trow1) * 128 + tc1 / 2);
        CP_ASYNC16(sb + 3 * MATB + SWZ256(trow0, tc0),
                   Bl + (long)(k0 + trow0) * 128 + tc0 / 2);
        CP_ASYNC16(sb + 3 * MATB + SWZ256(trow1, tc1),
                   Bl + (long)(k0 + trow1) * 128 + tc1 / 2);
    };

    const int tr_r = lane & 7, tr_q = lane >> 3;
    const int klB = (tr_q & 1) * 8 + tr_r;
    const int nbB = (tr_q >> 1) * 16;
    const int klA = (tr_q >> 1) * 8 + tr_r;
    const int mbA = (tr_q & 1) * 16;
    const int aRow = (lane & 7) + ((lane >> 3) & 1) * 8;
    const int aKB  = (lane >> 4) * 16;

    auto compute_chunk = [&](int stage) {
        const uint32_t sb  = smb + stage * STAGEB;
        const uint32_t tAh = sb;
        const uint32_t tAl = sb + MATB;
        const uint32_t tBh = sb + 2 * MATB;
        const uint32_t tBl = sb + 3 * MATB;
#pragma unroll
        for (int ks = 0; ks < 2; ks++) {
            uint32_t bh[4][2], bl[4][2];
#pragma unroll
            for (int nfb = 0; nfb < 4; nfb += 2) {
                const int kr = ks * 16 + klB;
                const int nb = (wn * 32 + nfb * 8) * 2 + nbB;
                uint32_t r[4];
                ldm_x4t(r, tBh + SWZ256(kr, nb));
                bh[nfb][0] = r[0]; bh[nfb][1] = r[1];
                bh[nfb + 1][0] = r[2]; bh[nfb + 1][1] = r[3];
                ldm_x4t(r, tBl + SWZ256(kr, nb));
                bl[nfb][0] = r[0]; bl[nfb][1] = r[1];
                bl[nfb + 1][0] = r[2]; bl[nfb + 1][1] = r[3];
            }
#pragma unroll
            for (int mf = 0; mf < 4; mf++) {
                uint32_t ah[4], al[4];
                if (trA) {
                    const int kr = ks * 16 + klA;
                    const int mb = (wm * 64 + mf * 16) * 2 + mbA;
                    ldm_x4t(ah, tAh + SWZ256(kr, mb));
                    ldm_x4t(al, tAl + SWZ256(kr, mb));
                } else {
                    const int rr = wm * 64 + mf * 16 + aRow;
                    const int kb = ks * 32 + aKB;
                    ldm_x4(ah, tAh + SWZ64(rr, kb));
                    ldm_x4(al, tAl + SWZ64(rr, kb));
                }
                // 3 passes: same-accumulator reuse distance = 4 MMAs
#pragma unroll
                for (int nf = 0; nf < 4; nf++) mma16816(acc[mf][nf], ah, bh[nf]);
#pragma unroll
                for (int nf = 0; nf < 4; nf++) mma16816(acc[mf][nf], ah, bl[nf]);
#pragma unroll
                for (int nf = 0; nf < 4; nf++) mma16816(acc[mf][nf], al, bh[nf]);
            }
        }
    };

    load_chunk(0, 0);
    CP_COMMIT();
    load_chunk(1, 1);
    CP_COMMIT();
    for (int c = 0; c < nch; c++) {
        if (c + 1 < nch) CP_WAIT1(); else CP_WAIT0();
        __syncthreads();
        if (c + 2 < nch) {
            load_chunk(c + 2, (c + 2) % 3);
            CP_COMMIT();
        }
        compute_chunk(c % 3);
    }

    // ---- epilogues ----
    if (OUTHL) {
#pragma unroll
        for (int mf = 0; mf < 4; mf++) {
#pragma unroll
            for (int nf = 0; nf < 4; nf++) {
                const int mr0 = m0 + wm * 64 + mf * 16 + g;
                const int mr1 = mr0 + 8;
                const int n0  = wn * 32 + nf * 8 + 2 * t;
                const float* cc = acc[mf][nf];
                bf16 h0, l0, h1, l1, h2, l2, h3, l3;
                split2(cc[0], h0, l0); split2(cc[1], h1, l1);
                split2(cc[2], h2, l2); split2(cc[3], h3, l3);
                if (mr0 < A.Mvalid) {
                    *(uint32_t*)(A.Chi + z * A.sHL + (long)mr0 * 128 + n0) =
                        pack_bf2(h0, h1);
                    *(uint32_t*)(A.Clo + z * A.sHL + (long)mr0 * 128 + n0) =
                        pack_bf2(l0, l1);
                }
                if (mr1 < A.Mvalid) {
                    *(uint32_t*)(A.Chi + z * A.sHL + (long)mr1 * 128 + n0) =
                        pack_bf2(h2, h3);
                    *(uint32_t*)(A.Clo + z * A.sHL + (long)mr1 * 128 + n0) =
                        pack_bf2(l2, l3);
                }
            }
        }
    }

    if (OUTS) {
        __syncthreads();                    // smem stages dead -> reuse
        float* part = (float*)sm;           // [4][128]
#pragma unroll
        for (int mf = 0; mf < 4; mf++) {
#pragma unroll
            for (int half = 0; half < 2; half++) {
                const int ml = wm * 64 + mf * 16 + half * 8 + g;
                const int mr = m0 + ml;
                float val = 0.f;
                if (mr < A.Mvalid) {
                    const bf16* uh = A.Uhi + z * A.sU + (long)mr * 128;
                    const bf16* ul = A.Ulo + z * A.sU + (long)mr * 128;
#pragma unroll
                    for (int nf = 0; nf < 4; nf++) {
                        const int n = wn * 32 + nf * 8 + 2 * t;
                        union { uint32_t u; bf16 h[2]; } H, L;
                        H.u = *(const uint32_t*)(uh + n);
                        L.u = *(const uint32_t*)(ul + n);
                        float u0 = __bfloat162float(H.h[0]) + __bfloat162float(L.h[0]);
                        float u1 = __bfloat162float(H.h[1]) + __bfloat162float(L.h[1]);
                        val += tanhf(u0 + acc[mf][nf][half * 2 + 0]) * s_wh[n];
                        val += tanhf(u1 + acc[mf][nf][half * 2 + 1]) * s_wh[n + 1];
                    }
                }
                val += __shfl_xor_sync(0xffffffffu, val, 1);
                val += __shfl_xor_sync(0xffffffffu, val, 2);
                if (t == 0) part[wn * 128 + ml] = val;
            }
        }
        __syncthreads();
        if (tid < 128) {
            const int mr = m0 + tid;
            if (mr < A.Mvalid) {
                float s = part[tid] + part[128 + tid] + part[256 + tid] + part[384 + tid];
                A.Sout[z * A.sS + mr] = s;
            }
        }
    }
}

// ===========================================================================
// Tail kernels
// ===========================================================================
__global__ void softmax_kernel(float* __restrict__ s, int L)
{
    float* row = s + (long)blockIdx.x * L;
    __shared__ float red[32];
    __shared__ float bval;
    const int tid  = threadIdx.x;
    const int lane = tid & 31;
    const int wid  = tid >> 5;
    const int nw   = blockDim.x >> 5;

    float m = -1e30f;
    for (int i = tid; i < L; i += blockDim.x) m = fmaxf(m, row[i]);
#pragma unroll
    for (int o = 16; o > 0; o >>= 1) m = fmaxf(m, __shfl_xor_sync(0xffffffffu, m, o));
    if (lane == 0) red[wid] = m;
    __syncthreads();
    if (tid == 0) {
        float mm = red[0];
        for (int w = 1; w < nw; w++) mm = fmaxf(mm, red[w]);
        bval = mm;
    }
    __syncthreads();
    m = bval;
    __syncthreads();

    float sum = 0.f;
    for (int i = tid; i < L; i += blockDim.x) {
        float e = expf(row[i] - m);
        row[i] = e;
        sum += e;
    }
#pragma unroll
    for (int o = 16; o > 0; o >>= 1) sum += __shfl_xor_sync(0xffffffffu, sum, o);
    if (lane == 0) red[wid] = sum;
    __syncthreads();
    if (tid == 0) {
        float ss = 0.f;
        for (int w = 0; w < nw; w++) ss += red[w];
        bval = ss;
    }
    __syncthreads();
    float inv = 1.f / bval;
    for (int i = tid; i < L; i += blockDim.x) row[i] *= inv;
}

__global__ void __launch_bounds__(768) context_kernel(
    const float* __restrict__ T, const float* __restrict__ I,
    const float* __restrict__ aq, const float* __restrict__ av,
    float* __restrict__ ctx)
{
    __shared__ float sq[cfg::LT];
    __shared__ float sv[cfg::LV];
    const int b = blockIdx.x;
    const int d = threadIdx.x;
    for (int i = d; i < cfg::LT; i += 768) sq[i] = aq[(long)b * cfg::LT + i];
    if (d < cfg::LV) sv[d] = av[(long)b * cfg::LV + d];
    __syncthreads();

    const float* Ib = I + (long)b * cfg::LV * cfg::E + d;
    const float* Tb = T + (long)b * cfg::LT * cfg::E + d;
    float acc = 0.f;
#pragma unroll 4
    for (int y = 0; y < cfg::LV; y++) acc += sv[y] * Ib[(long)y * cfg::E];
#pragma unroll 4
    for (int x = 0; x < cfg::LT; x++) acc += sq[x] * Tb[(long)x * cfg::E];
    ctx[(long)b * cfg::E + d] = acc;
}

__global__ void __launch_bounds__(768) out_kernel(
    const float* __restrict__ ctx, const float* __restrict__ ws,
    float* __restrict__ out)
{
    __shared__ float sc[cfg::E];
    const int b = blockIdx.x;
    const int e = threadIdx.x;
    sc[e] = ctx[(long)b * cfg::E + e];
    __syncthreads();
    float acc = 0.f;
#pragma unroll 8
    for (int d = 0; d < cfg::E; d++)
        acc += sc[d] * ws[(long)d * cfg::E + e];
    out[(long)b * cfg::E + e] = tanhf(acc);
}

// ===========================================================================
// launch
// ===========================================================================
extern "C" void kernel_launch(void* const* d_in, const int* in_sizes, int n_in,
                              void* d_out, int out_size)
{
    using namespace cfg;
    const float* T   = (const float*)d_in[0];
    const float* I   = (const float*)d_in[1];
    const float* wb  = (const float*)d_in[3];
    const float* wv  = (const float*)d_in[4];
    const float* wq  = (const float*)d_in[5];
    const float* whv = (const float*)d_in[6];
    const float* whq = (const float*)d_in[7];
    const float* ws  = (const float*)d_in[8];
    float* out = (float*)d_out;

    bf16 *Thi, *Tlo, *Ihi, *Ilo, *wbhi, *wblo, *wqhi, *wqlo, *wvhi, *wvlo;
    bf16 *wqqhi, *wqqlo, *wvvhi, *wvvlo;
    bf16 *A1hi, *A1lo, *M1hi, *M1lo, *A2hi, *A2lo, *Hhi, *Hlo;
    float *sv, *sq, *ctx;

    cudaGetSymbolAddress((void**)&Thi, g_Thi);   cudaGetSymbolAddress((void**)&Tlo, g_Tlo);
    cudaGetSymbolAddress((void**)&Ihi, g_Ihi);   cudaGetSymbolAddress((void**)&Ilo, g_Ilo);
    cudaGetSymbolAddress((void**)&wbhi, g_wbhi); cudaGetSymbolAddress((void**)&wblo, g_wblo);
    cudaGetSymbolAddress((void**)&wqhi, g_wqhi); cudaGetSymbolAddress((void**)&wqlo, g_wqlo);
    cudaGetSymbolAddress((void**)&wvhi, g_wvhi); cudaGetSymbolAddress((void**)&wvlo, g_wvlo);
    cudaGetSymbolAddress((void**)&wqqhi, g_wqqhi); cudaGetSymbolAddress((void**)&wqqlo, g_wqqlo);
    cudaGetSymbolAddress((void**)&wvvhi, g_wvvhi); cudaGetSymbolAddress((void**)&wvvlo, g_wvvlo);
    cudaGetSymbolAddress((void**)&A1hi, g_A1hi); cudaGetSymbolAddress((void**)&A1lo, g_A1lo);
    cudaGetSymbolAddress((void**)&M1hi, g_M1hi); cudaGetSymbolAddress((void**)&M1lo, g_M1lo);
    cudaGetSymbolAddress((void**)&A2hi, g_A2hi); cudaGetSymbolAddress((void**)&A2lo, g_A2lo);
    cudaGetSymbolAddress((void**)&Hhi, g_Hhi);   cudaGetSymbolAddress((void**)&Hlo, g_Hlo);
    cudaGetSymbolAddress((void**)&sv, g_sv);     cudaGetSymbolAddress((void**)&sq, g_sq);
    cudaGetSymbolAddress((void**)&ctx, g_ctx);

    cudaFuncSetAttribute(mma_gemm<true, false>,
        cudaFuncAttributeMaxDynamicSharedMemorySize, SMEM_MMA_BYTES);
    cudaFuncSetAttribute(mma_gemm<false, true>,
        cudaFuncAttributeMaxDynamicSharedMemorySize, SMEM_MMA_BYTES);

    // --- conversions (flat hi/lo only) ---
    {
        long nT = (long)Bn * LT * E / 4, nI = (long)Bn * LV * E / 4;
        long nWb = (long)E * E / 4, nW = (long)E * Kd / 4;
        conv_flat<<<(unsigned)((nT + 255) / 256), 256>>>(T, Thi, Tlo, nT);
        conv_flat<<<(unsigned)((nI + 255) / 256), 256>>>(I, Ihi, Ilo, nI);
        conv_flat<<<(unsigned)((nWb + 255) / 256), 256>>>(wb, wbhi, wblo, nWb);
        conv_flat<<<(unsigned)((nW + 255) / 256), 256>>>(wq, wqhi, wqlo, nW);
        conv_flat<<<(unsigned)((nW + 255) / 256), 256>>>(wv, wvhi, wvlo, nW);
    }

    GArgs Z{};

    // L1: G1 wqq = T@wq (flat M=65536) | G2 wvv = I@wv (flat M=36864)
    {
        GArgs a0 = Z, a1 = Z;
        a0.Ahi = Thi; a0.Alo = Tlo; a0.Bhi = wqhi; a0.Blo = wqlo;
        a0.Chi = wqqhi; a0.Clo = wqqlo;
        a0.Ktot = E; a0.Mvalid = Bn * LT;
        a1.Ahi = Ihi; a1.Alo = Ilo; a1.Bhi = wvhi; a1.Blo = wvlo;
        a1.Chi = wvvhi; a1.Clo = wvvlo;
        a1.Ktot = E; a1.Mvalid = Bn * LV;
        mma_gemm<true, false><<<dim3(512 + 288, 1, 1), 256, SMEM_MMA_BYTES>>>(
            a0, a1, 512);
    }
    // L2: G3 A1 = T^T@wqq (transA, K=1024) | G6 A2 = I^T@wvv (transA, K=576)
    {
        GArgs a0 = Z, a1 = Z;
        a0.Ahi = Thi; a0.Alo = Tlo; a0.sA = (long)LT * E; a0.transA = 1;
        a0.Bhi = wqqhi; a0.Blo = wqqlo; a0.sB = (long)LT * Kd;
        a0.Chi = A1hi; a0.Clo = A1lo; a0.sHL = (long)E * Kd;
        a0.Ktot = LT; a0.Mvalid = E;
        a1.Ahi = Ihi; a1.Alo = Ilo; a1.sA = (long)LV * E; a1.transA = 1;
        a1.Bhi = wvvhi; a1.Blo = wvvlo; a1.sB = (long)LV * Kd;
        a1.Chi = A2hi; a1.Clo = A2lo; a1.sHL = (long)E * Kd;
        a1.Ktot = LV; a1.Mvalid = E;
        mma_gemm<true, false><<<dim3(12, 1, Bn), 256, SMEM_MMA_BYTES>>>(
            a0, a1, 6);
    }
    // L3: G4 M1 = wb^T@A1 (transA) | G7 H = wb@A2 (normal A)
    {
        GArgs a0 = Z, a1 = Z;
        a0.Ahi = wbhi; a0.Alo = wblo; a0.transA = 1;
        a0.Bhi = A1hi; a0.Blo = A1lo; a0.sB = (long)E * Kd;
        a0.Chi = M1hi; a0.Clo = M1lo; a0.sHL = (long)E * Kd;
        a0.Ktot = E; a0.Mvalid = E;
        a1.Ahi = wbhi; a1.Alo = wblo; a1.transA = 0;
        a1.Bhi = A2hi; a1.Blo = A2lo; a1.sB = (long)E * Kd;
        a1.Chi = Hhi; a1.Clo = Hlo; a1.sHL = (long)E * Kd;
        a1.Ktot = E; a1.Mvalid = E;
        mma_gemm<true, false><<<dim3(12, 1, Bn), 256, SMEM_MMA_BYTES>>>(
            a0, a1, 6);
    }
    // L4: G5 sv = score(I@M1 + wvv) | G8 sq = score(T@H + wqq)
    {
        GArgs a0 = Z, a1 = Z;
        a0.Ahi = Ihi; a0.Alo = Ilo; a0.sA = (long)LV * E;
        a0.Bhi = M1hi; a0.Blo = M1lo; a0.sB = (long)E * Kd;
        a0.Uhi = wvvhi; a0.Ulo = wvvlo; a0.sU = (long)LV * Kd; a0.wh = whv;
        a0.Sout = sv; a0.sS = LV;
        a0.Ktot = E; a0.Mvalid = LV;
        a1.Ahi = Thi; a1.Alo = Tlo; a1.sA = (long)LT * E;
        a1.Bhi = Hhi; a1.Blo = Hlo; a1.sB = (long)E * Kd;
        a1.Uhi = wqqhi; a1.Ulo = wqqlo; a1.sU = (long)LT * Kd; a1.wh = whq;
        a1.Sout = sq; a1.sS = LT;
        a1.Ktot = E; a1.Mvalid = LT;
        mma_gemm<false, true><<<dim3(5 + 8, 1, Bn), 256, SMEM_MMA_BYTES>>>(
            a0, a1, 5);
    }

    // --- softmax / context / output ---
    softmax_kernel<<<Bn, 256>>>(sv, LV);
    softmax_kernel<<<Bn, 256>>>(sq, LT);
    context_kernel<<<Bn, 768>>>(T, I, sq, sv, ctx);
    out_kernel<<<Bn, 768>>>(ctx, ws, out);
}

// round 10
// speedup vs baseline: 1.1873x; 1.1873x over previous
#include <cuda_runtime.h>
#include <cuda_bf16.h>
#include <math.h>
#include <stdint.h>

// Problem constants: B=64, LT=1024, LV=576, E=768, K=128
namespace cfg {
constexpr int Bn = 64;
constexpr int LT = 1024;
constexpr int LV = 576;
constexpr int E  = 768;
constexpr int Kd = 128;
constexpr int NP = 8;    // context partial slices
}
using bf16 = __nv_bfloat16;

__device__ __forceinline__ void split2(float v, bf16& h, bf16& l) {
    h = __float2bfloat16(v);
    l = __float2bfloat16(v - __bfloat162float(h));
}

__device__ __forceinline__ uint32_t pack_bf2(bf16 a, bf16 b) {
    union { bf16 h[2]; uint32_t u; } w;
    w.h[0] = a; w.h[1] = b;
    return w.u;
}

__device__ __forceinline__ void mma16816(float* d, const uint32_t* a, const uint32_t* b) {
    asm volatile(
        "mma.sync.aligned.m16n8k16.row.col.f32.bf16.bf16.f32 "
        "{%0,%1,%2,%3}, {%4,%5,%6,%7}, {%8,%9}, {%0,%1,%2,%3};"
        : "+f"(d[0]), "+f"(d[1]), "+f"(d[2]), "+f"(d[3])
        : "r"(a[0]), "r"(a[1]), "r"(a[2]), "r"(a[3]), "r"(b[0]), "r"(b[1]));
}

__device__ __forceinline__ void ldm_x4(uint32_t* r, uint32_t saddr) {
    asm volatile("ldmatrix.sync.aligned.m8n8.x4.shared.b16 {%0,%1,%2,%3}, [%4];"
        : "=r"(r[0]), "=r"(r[1]), "=r"(r[2]), "=r"(r[3]) : "r"(saddr));
}
__device__ __forceinline__ void ldm_x4t(uint32_t* r, uint32_t saddr) {
    asm volatile("ldmatrix.sync.aligned.m8n8.x4.trans.shared.b16 {%0,%1,%2,%3}, [%4];"
        : "=r"(r[0]), "=r"(r[1]), "=r"(r[2]), "=r"(r[3]) : "r"(saddr));
}

__device__ __forceinline__ uint32_t smem_u32(const void* p) {
    uint32_t a;
    asm("{ .reg .u64 t; cvta.to.shared.u64 t, %1; cvt.u32.u64 %0, t; }"
        : "=r"(a) : "l"(p));
    return a;
}

#define CP_ASYNC16(s, g) \
    asm volatile("cp.async.cg.shared.global [%0], [%1], 16;" :: "r"(s), "l"(g))
#define CP_COMMIT() asm volatile("cp.async.commit_group;")
#define CP_WAIT1()  asm volatile("cp.async.wait_group 1;")
#define CP_WAIT0()  asm volatile("cp.async.wait_group 0;")

#define SWZ64(row, kb)  ((uint32_t)((row) * 64  + ((kb) ^ (((row) & 3) << 4))))
#define SWZ256(row, kb) ((uint32_t)((row) * 256 + ((kb) ^ (((row) & 7) << 4))))

// ===========================================================================
// Scratch (device globals; zero-initialized)
// ===========================================================================
#define DEV_BF16(name, n) __device__ __align__(256) bf16 name[n]
DEV_BF16(g_Thi,  64 * 1024 * 768);
DEV_BF16(g_Tlo,  64 * 1024 * 768);
DEV_BF16(g_Ihi,  64 * 576 * 768 + 64 * 768);   // +pad: GEMM5 reads 64 extra rows
DEV_BF16(g_Ilo,  64 * 576 * 768 + 64 * 768);
DEV_BF16(g_wbhi,  768 * 768);
DEV_BF16(g_wblo,  768 * 768);
DEV_BF16(g_wqhi,  768 * 128);
DEV_BF16(g_wqlo,  768 * 128);
DEV_BF16(g_wvhi,  768 * 128);
DEV_BF16(g_wvlo,  768 * 128);
DEV_BF16(g_wqqhi, 64 * 1024 * 128);
DEV_BF16(g_wqqlo, 64 * 1024 * 128);
DEV_BF16(g_wvvhi, 64 * 576 * 128);
DEV_BF16(g_wvvlo, 64 * 576 * 128);
DEV_BF16(g_A1hi,  64 * 768 * 128);
DEV_BF16(g_A1lo,  64 * 768 * 128);
DEV_BF16(g_M1hi,  64 * 768 * 128);
DEV_BF16(g_M1lo,  64 * 768 * 128);
DEV_BF16(g_A2hi,  64 * 768 * 128);
DEV_BF16(g_A2lo,  64 * 768 * 128);
DEV_BF16(g_Hhi,   64 * 768 * 128);
DEV_BF16(g_Hlo,   64 * 768 * 128);

__device__ float g_sv  [cfg::Bn * cfg::LV];
__device__ float g_sq  [cfg::Bn * cfg::LT];
__device__ float g_ctxp[cfg::Bn * cfg::NP * cfg::E];

// ===========================================================================
// Flat conversion: fp32 -> bf16 hi/lo
// ===========================================================================
__global__ void conv_flat(const float* __restrict__ X,
                          bf16* __restrict__ hi, bf16* __restrict__ lo, long n4)
{
    long idx = (long)blockIdx.x * blockDim.x + threadIdx.x;
    if (idx >= n4) return;
    float4 v = ((const float4*)X)[idx];
    union { bf16 h[4]; uint2 u; } H, L;
    split2(v.x, H.h[0], L.h[0]);
    split2(v.y, H.h[1], L.h[1]);
    split2(v.z, H.h[2], L.h[2]);
    split2(v.w, H.h[3], L.h[3]);
    ((uint2*)hi)[idx] = H.u;
    ((uint2*)lo)[idx] = L.u;
}

// ===========================================================================
// Merged-pair HMMA batched GEMM: C[M,128] = op(A)[M,K] @ B[K,128]
// ===========================================================================
constexpr int MATB   = 8192;
constexpr int STAGEB = 4 * MATB;
static constexpr int SMEM_MMA_BYTES = 3 * STAGEB;   // 98304 B

struct GArgs {
    const bf16 *Ahi, *Alo, *Bhi, *Blo;
    long sA, sB, sHL, sU, sS;
    bf16 *Chi, *Clo;
    const bf16 *Uhi, *Ulo;
    const float* wh;
    float* Sout;
    int Ktot, Mvalid, transA;
};

template <bool OUTHL, bool OUTS>
__global__ void __launch_bounds__(256, 2) mma_gemm(GArgs a0, GArgs a1, int splitX)
{
    extern __shared__ __align__(16) bf16 sm[];
    __shared__ float s_wh[128];
    const uint32_t smb = smem_u32(sm);

    const GArgs& A = (blockIdx.x < (unsigned)splitX) ? a0 : a1;
    const int bx = (blockIdx.x < (unsigned)splitX) ? blockIdx.x
                                                   : blockIdx.x - splitX;

    const int tid  = threadIdx.x;
    const int lane = tid & 31;
    const int wid  = tid >> 5;
    const int wm   = wid & 1;
    const int wn   = wid >> 1;
    const int g    = lane >> 2;
    const int t    = lane & 3;

    const long z    = blockIdx.z;
    const int  m0   = bx * 128;
    const int  Ktot = A.Ktot;
    const bool trA  = (A.transA != 0);

    if (OUTS && tid < 128) s_wh[tid] = A.wh[tid];

    const bf16* Ah = A.Ahi + z * A.sA + (trA ? 0 : (long)m0 * 768);
    const bf16* Al = A.Alo + z * A.sA + (trA ? 0 : (long)m0 * 768);
    const bf16* Bh = A.Bhi + z * A.sB;
    const bf16* Bl = A.Blo + z * A.sB;

    float acc[4][4][4];
#pragma unroll
    for (int i = 0; i < 4; i++)
#pragma unroll
        for (int j = 0; j < 4; j++)
#pragma unroll
            for (int q = 0; q < 4; q++) acc[i][j][q] = 0.f;

    const int nch = Ktot >> 5;

    const int nrow0 = (tid * 2)     >> 2, nc0 = ((tid * 2)     & 3) * 16;
    const int nrow1 = (tid * 2 + 1) >> 2, nc1 = ((tid * 2 + 1) & 3) * 16;
    const int trow0 = (tid * 2)     >> 4, tc0 = ((tid * 2)     & 15) * 16;
    const int trow1 = (tid * 2 + 1) >> 4, tc1 = ((tid * 2 + 1) & 15) * 16;

    auto load_chunk = [&](int c, int stage) {
        const int k0 = c << 5;
        const uint32_t sb = smb + stage * STAGEB;
        if (trA) {
            CP_ASYNC16(sb + SWZ256(trow0, tc0),
                       Ah + (long)(k0 + trow0) * 768 + m0 + tc0 / 2);
            CP_ASYNC16(sb + SWZ256(trow1, tc1),
                       Ah + (long)(k0 + trow1) * 768 + m0 + tc1 / 2);
            CP_ASYNC16(sb + MATB + SWZ256(trow0, tc0),
                       Al + (long)(k0 + trow0) * 768 + m0 + tc0 / 2);
            CP_ASYNC16(sb + MATB + SWZ256(trow1, tc1),
                       Al + (long)(k0 + trow1) * 768 + m0 + tc1 / 2);
        } else {
            CP_ASYNC16(sb + SWZ64(nrow0, nc0),
                       Ah + (long)nrow0 * 768 + k0 + nc0 / 2);
            CP_ASYNC16(sb + SWZ64(nrow1, nc1),
                       Ah + (long)nrow1 * 768 + k0 + nc1 / 2);
            CP_ASYNC16(sb + MATB + SWZ64(nrow0, nc0),
                       Al + (long)nrow0 * 768 + k0 + nc0 / 2);
            CP_ASYNC16(sb + MATB + SWZ64(nrow1, nc1),
                       Al + (long)nrow1 * 768 + k0 + nc1 / 2);
        }
        CP_ASYNC16(sb + 2 * MATB + SWZ256(trow0, tc0),
                   Bh + (long)(k0 + trow0) * 128 + tc0 / 2);
        CP_ASYNC16(sb + 2 * MATB + SWZ256(trow1, tc1),
                   Bh + (long)(k0 + trow1) * 128 + tc1 / 2);
        CP_ASYNC16(sb + 3 * MATB + SWZ256(trow0, tc0),
                   Bl + (long)(k0 + trow0) * 128 + tc0 / 2);
        CP_ASYNC16(sb + 3 * MATB + SWZ256(trow1, tc1),
                   Bl + (long)(k0 + trow1) * 128 + tc1 / 2);
    };

    const int tr_r = lane & 7, tr_q = lane >> 3;
    const int klB = (tr_q & 1) * 8 + tr_r;
    const int nbB = (tr_q >> 1) * 16;
    const int klA = (tr_q >> 1) * 8 + tr_r;
    const int mbA = (tr_q & 1) * 16;
    const int aRow = (lane & 7) + ((lane >> 3) & 1) * 8;
    const int aKB  = (lane >> 4) * 16;

    auto compute_chunk = [&](int stage) {
        const uint32_t sb  = smb + stage * STAGEB;
        const uint32_t tAh = sb;
        const uint32_t tAl = sb + MATB;
        const uint32_t tBh = sb + 2 * MATB;
        const uint32_t tBl = sb + 3 * MATB;
#pragma unroll
        for (int ks = 0; ks < 2; ks++) {
            uint32_t bh[4][2], bl[4][2];
#pragma unroll
            for (int nfb = 0; nfb < 4; nfb += 2) {
                const int kr = ks * 16 + klB;
                const int nb = (wn * 32 + nfb * 8) * 2 + nbB;
                uint32_t r[4];
                ldm_x4t(r, tBh + SWZ256(kr, nb));
                bh[nfb][0] = r[0]; bh[nfb][1] = r[1];
                bh[nfb + 1][0] = r[2]; bh[nfb + 1][1] = r[3];
                ldm_x4t(r, tBl + SWZ256(kr, nb));
                bl[nfb][0] = r[0]; bl[nfb][1] = r[1];
                bl[nfb + 1][0] = r[2]; bl[nfb + 1][1] = r[3];
            }
#pragma unroll
            for (int mf = 0; mf < 4; mf++) {
                uint32_t ah[4], al[4];
                if (trA) {
                    const int kr = ks * 16 + klA;
                    const int mb = (wm * 64 + mf * 16) * 2 + mbA;
                    ldm_x4t(ah, tAh + SWZ256(kr, mb));
                    ldm_x4t(al, tAl + SWZ256(kr, mb));
                } else {
                    const int rr = wm * 64 + mf * 16 + aRow;
                    const int kb = ks * 32 + aKB;
                    ldm_x4(ah, tAh + SWZ64(rr, kb));
                    ldm_x4(al, tAl + SWZ64(rr, kb));
                }
                // interleaved grouping (round-8 ordering; measured faster)
#pragma unroll
                for (int nf = 0; nf < 4; nf++) {
                    mma16816(acc[mf][nf], ah, bh[nf]);
                    mma16816(acc[mf][nf], ah, bl[nf]);
                    mma16816(acc[mf][nf], al, bh[nf]);
                }
            }
        }
    };

    load_chunk(0, 0);
    CP_COMMIT();
    load_chunk(1, 1);
    CP_COMMIT();
    for (int c = 0; c < nch; c++) {
        if (c + 1 < nch) CP_WAIT1(); else CP_WAIT0();
        __syncthreads();
        if (c + 2 < nch) {
            load_chunk(c + 2, (c + 2) % 3);
            CP_COMMIT();
        }
        compute_chunk(c % 3);
    }

    // ---- epilogues ----
    if (OUTHL) {
#pragma unroll
        for (int mf = 0; mf < 4; mf++) {
#pragma unroll
            for (int nf = 0; nf < 4; nf++) {
                const int mr0 = m0 + wm * 64 + mf * 16 + g;
                const int mr1 = mr0 + 8;
                const int n0  = wn * 32 + nf * 8 + 2 * t;
                const float* cc = acc[mf][nf];
                bf16 h0, l0, h1, l1, h2, l2, h3, l3;
                split2(cc[0], h0, l0); split2(cc[1], h1, l1);
                split2(cc[2], h2, l2); split2(cc[3], h3, l3);
                if (mr0 < A.Mvalid) {
                    *(uint32_t*)(A.Chi + z * A.sHL + (long)mr0 * 128 + n0) =
                        pack_bf2(h0, h1);
                    *(uint32_t*)(A.Clo + z * A.sHL + (long)mr0 * 128 + n0) =
                        pack_bf2(l0, l1);
                }
                if (mr1 < A.Mvalid) {
                    *(uint32_t*)(A.Chi + z * A.sHL + (long)mr1 * 128 + n0) =
                        pack_bf2(h2, h3);
                    *(uint32_t*)(A.Clo + z * A.sHL + (long)mr1 * 128 + n0) =
                        pack_bf2(l2, l3);
                }
            }
        }
    }

    if (OUTS) {
        __syncthreads();                    // smem stages dead -> reuse
        float* part = (float*)sm;           // [4][128]
#pragma unroll
        for (int mf = 0; mf < 4; mf++) {
#pragma unroll
            for (int half = 0; half < 2; half++) {
                const int ml = wm * 64 + mf * 16 + half * 8 + g;
                const int mr = m0 + ml;
                float val = 0.f;
                if (mr < A.Mvalid) {
                    const bf16* uh = A.Uhi + z * A.sU + (long)mr * 128;
                    const bf16* ul = A.Ulo + z * A.sU + (long)mr * 128;
#pragma unroll
                    for (int nf = 0; nf < 4; nf++) {
                        const int n = wn * 32 + nf * 8 + 2 * t;
                        union { uint32_t u; bf16 h[2]; } H, L;
                        H.u = *(const uint32_t*)(uh + n);
                        L.u = *(const uint32_t*)(ul + n);
                        float u0 = __bfloat162float(H.h[0]) + __bfloat162float(L.h[0]);
                        float u1 = __bfloat162float(H.h[1]) + __bfloat162float(L.h[1]);
                        val += tanhf(u0 + acc[mf][nf][half * 2 + 0]) * s_wh[n];
                        val += tanhf(u1 + acc[mf][nf][half * 2 + 1]) * s_wh[n + 1];
                    }
                }
                val += __shfl_xor_sync(0xffffffffu, val, 1);
                val += __shfl_xor_sync(0xffffffffu, val, 2);
                if (t == 0) part[wn * 128 + ml] = val;
            }
        }
        __syncthreads();
        if (tid < 128) {
            const int mr = m0 + tid;
            if (mr < A.Mvalid) {
                float s = part[tid] + part[128 + tid] + part[256 + tid] + part[384 + tid];
                A.Sout[z * A.sS + mr] = s;
            }
        }
    }
}

// ===========================================================================
// Tail kernels
// ===========================================================================
// both softmaxes in one launch: blocks 0..63 -> sv (L=576), 64..127 -> sq (L=1024)
__global__ void softmax2_kernel(float* __restrict__ svp, float* __restrict__ sqp)
{
    const bool isv = blockIdx.x < cfg::Bn;
    const int  b   = isv ? blockIdx.x : blockIdx.x - cfg::Bn;
    const int  L   = isv ? cfg::LV : cfg::LT;
    float* row = (isv ? svp : sqp) + (long)b * L;

    __shared__ float red[32];
    __shared__ float bval;
    const int tid  = threadIdx.x;
    const int lane = tid & 31;
    const int wid  = tid >> 5;
    const int nw   = blockDim.x >> 5;

    float m = -1e30f;
    for (int i = tid; i < L; i += blockDim.x) m = fmaxf(m, row[i]);
#pragma unroll
    for (int o = 16; o > 0; o >>= 1) m = fmaxf(m, __shfl_xor_sync(0xffffffffu, m, o));
    if (lane == 0) red[wid] = m;
    __syncthreads();
    if (tid == 0) {
        float mm = red[0];
        for (int w = 1; w < nw; w++) mm = fmaxf(mm, red[w]);
        bval = mm;
    }
    __syncthreads();
    m = bval;
    __syncthreads();

    float sum = 0.f;
    for (int i = tid; i < L; i += blockDim.x) {
        float e = expf(row[i] - m);
        row[i] = e;
        sum += e;
    }
#pragma unroll
    for (int o = 16; o > 0; o >>= 1) sum += __shfl_xor_sync(0xffffffffu, sum, o);
    if (lane == 0) red[wid] = sum;
    __syncthreads();
    if (tid == 0) {
        float ss = 0.f;
        for (int w = 0; w < nw; w++) ss += red[w];
        bval = ss;
    }
    __syncthreads();
    float inv = 1.f / bval;
    for (int i = tid; i < L; i += blockDim.x) row[i] *= inv;
}

// partial context: grid (Bn, NP); slice p covers LV/NP image rows + LT/NP text rows
__global__ void __launch_bounds__(768) context_part(
    const float* __restrict__ T, const float* __restrict__ I,
    const float* __restrict__ aq, const float* __restrict__ av,
    float* __restrict__ ctxp)
{
    constexpr int YS = cfg::LV / cfg::NP;   // 72
    constexpr int XS = cfg::LT / cfg::NP;   // 128
    __shared__ float sq[XS];
    __shared__ float sv[YS];
    const int b = blockIdx.x;
    const int p = blockIdx.y;
    const int d = threadIdx.x;
    if (d < XS) sq[d] = aq[(long)b * cfg::LT + p * XS + d];
    if (d < YS) sv[d] = av[(long)b * cfg::LV + p * YS + d];
    __syncthreads();

    const float* Ib = I + (long)b * cfg::LV * cfg::E + (long)(p * YS) * cfg::E + d;
    const float* Tb = T + (long)b * cfg::LT * cfg::E + (long)(p * XS) * cfg::E + d;
    float acc = 0.f;
#pragma unroll 4
    for (int y = 0; y < YS; y++) acc += sv[y] * Ib[(long)y * cfg::E];
#pragma unroll 4
    for (int x = 0; x < XS; x++) acc += sq[x] * Tb[(long)x * cfg::E];
    ctxp[((long)b * cfg::NP + p) * cfg::E + d] = acc;
}

__global__ void __launch_bounds__(768) out_kernel(
    const float* __restrict__ ctxp, const float* __restrict__ ws,
    float* __restrict__ out)
{
    __shared__ float sc[cfg::E];
    const int b = blockIdx.x;
    const int e = threadIdx.x;
    float c = 0.f;
#pragma unroll
    for (int p = 0; p < cfg::NP; p++)
        c += ctxp[((long)b * cfg::NP + p) * cfg::E + e];
    sc[e] = c;
    __syncthreads();
    float acc = 0.f;
#pragma unroll 8
    for (int d = 0; d < cfg::E; d++)
        acc += sc[d] * ws[(long)d * cfg::E + e];
    out[(long)b * cfg::E + e] = tanhf(acc);
}

// ===========================================================================
// launch
// ===========================================================================
extern "C" void kernel_launch(void* const* d_in, const int* in_sizes, int n_in,
                              void* d_out, int out_size)
{
    using namespace cfg;
    const float* T   = (const float*)d_in[0];
    const float* I   = (const float*)d_in[1];
    const float* wb  = (const float*)d_in[3];
    const float* wv  = (const float*)d_in[4];
    const float* wq  = (const float*)d_in[5];
    const float* whv = (const float*)d_in[6];
    const float* whq = (const float*)d_in[7];
    const float* ws  = (const float*)d_in[8];
    float* out = (float*)d_out;

    bf16 *Thi, *Tlo, *Ihi, *Ilo, *wbhi, *wblo, *wqhi, *wqlo, *wvhi, *wvlo;
    bf16 *wqqhi, *wqqlo, *wvvhi, *wvvlo;
    bf16 *A1hi, *A1lo, *M1hi, *M1lo, *A2hi, *A2lo, *Hhi, *Hlo;
    float *sv, *sq, *ctxp;

    cudaGetSymbolAddress((void**)&Thi, g_Thi);   cudaGetSymbolAddress((void**)&Tlo, g_Tlo);
    cudaGetSymbolAddress((void**)&Ihi, g_Ihi);   cudaGetSymbolAddress((void**)&Ilo, g_Ilo);
    cudaGetSymbolAddress((void**)&wbhi, g_wbhi); cudaGetSymbolAddress((void**)&wblo, g_wblo);
    cudaGetSymbolAddress((void**)&wqhi, g_wqhi); cudaGetSymbolAddress((void**)&wqlo, g_wqlo);
    cudaGetSymbolAddress((void**)&wvhi, g_wvhi); cudaGetSymbolAddress((void**)&wvlo, g_wvlo);
    cudaGetSymbolAddress((void**)&wqqhi, g_wqqhi); cudaGetSymbolAddress((void**)&wqqlo, g_wqqlo);
    cudaGetSymbolAddress((void**)&wvvhi, g_wvvhi); cudaGetSymbolAddress((void**)&wvvlo, g_wvvlo);
    cudaGetSymbolAddress((void**)&A1hi, g_A1hi); cudaGetSymbolAddress((void**)&A1lo, g_A1lo);
    cudaGetSymbolAddress((void**)&M1hi, g_M1hi); cudaGetSymbolAddress((void**)&M1lo, g_M1lo);
    cudaGetSymbolAddress((void**)&A2hi, g_A2hi); cudaGetSymbolAddress((void**)&A2lo, g_A2lo);
    cudaGetSymbolAddress((void**)&Hhi, g_Hhi);   cudaGetSymbolAddress((void**)&Hlo, g_Hlo);
    cudaGetSymbolAddress((void**)&sv, g_sv);     cudaGetSymbolAddress((void**)&sq, g_sq);
    cudaGetSymbolAddress((void**)&ctxp, g_ctxp);

    cudaFuncSetAttribute(mma_gemm<true, false>,
        cudaFuncAttributeMaxDynamicSharedMemorySize, SMEM_MMA_BYTES);
    cudaFuncSetAttribute(mma_gemm<false, true>,
        cudaFuncAttributeMaxDynamicSharedMemorySize, SMEM_MMA_BYTES);

    // --- conversions ---
    {
        long nT = (long)Bn * LT * E / 4, nI = (long)Bn * LV * E / 4;
        long nWb = (long)E * E / 4, nW = (long)E * Kd / 4;
        conv_flat<<<(unsigned)((nT + 255) / 256), 256>>>(T, Thi, Tlo, nT);
        conv_flat<<<(unsigned)((nI + 255) / 256), 256>>>(I, Ihi, Ilo, nI);
        conv_flat<<<(unsigned)((nWb + 255) / 256), 256>>>(wb, wbhi, wblo, nWb);
        conv_flat<<<(unsigned)((nW + 255) / 256), 256>>>(wq, wqhi, wqlo, nW);
        conv_flat<<<(unsigned)((nW + 255) / 256), 256>>>(wv, wvhi, wvlo, nW);
    }

    GArgs Z{};

    // L1: G1 wqq = T@wq | G2 wvv = I@wv
    {
        GArgs a0 = Z, a1 = Z;
        a0.Ahi = Thi; a0.Alo = Tlo; a0.Bhi = wqhi; a0.Blo = wqlo;
        a0.Chi = wqqhi; a0.Clo = wqqlo;
        a0.Ktot = E; a0.Mvalid = Bn * LT;
        a1.Ahi = Ihi; a1.Alo = Ilo; a1.Bhi = wvhi; a1.Blo = wvlo;
        a1.Chi = wvvhi; a1.Clo = wvvlo;
        a1.Ktot = E; a1.Mvalid = Bn * LV;
        mma_gemm<true, false><<<dim3(512 + 288, 1, 1), 256, SMEM_MMA_BYTES>>>(
            a0, a1, 512);
    }
    // L2: G3 A1 = T^T@wqq (transA, K=1024) | G6 A2 = I^T@wvv (transA, K=576)
    {
        GArgs a0 = Z, a1 = Z;
        a0.Ahi = Thi; a0.Alo = Tlo; a0.sA = (long)LT * E; a0.transA = 1;
        a0.Bhi = wqqhi; a0.Blo = wqqlo; a0.sB = (long)LT * Kd;
        a0.Chi = A1hi; a0.Clo = A1lo; a0.sHL = (long)E * Kd;
        a0.Ktot = LT; a0.Mvalid = E;
        a1.Ahi = Ihi; a1.Alo = Ilo; a1.sA = (long)LV * E; a1.transA = 1;
        a1.Bhi = wvvhi; a1.Blo = wvvlo; a1.sB = (long)LV * Kd;
        a1.Chi = A2hi; a1.Clo = A2lo; a1.sHL = (long)E * Kd;
        a1.Ktot = LV; a1.Mvalid = E;
        mma_gemm<true, false><<<dim3(12, 1, Bn), 256, SMEM_MMA_BYTES>>>(
            a0, a1, 6);
    }
    // L3: G4 M1 = wb^T@A1 (transA) | G7 H = wb@A2 (normal A)
    {
        GArgs a0 = Z, a1 = Z;
        a0.Ahi = wbhi; a0.Alo = wblo; a0.transA = 1;
        a0.Bhi = A1hi; a0.Blo = A1lo; a0.sB = (long)E * Kd;
        a0.Chi = M1hi; a0.Clo = M1lo; a0.sHL = (long)E * Kd;
        a0.Ktot = E; a0.Mvalid = E;
        a1.Ahi = wbhi; a1.Alo = wblo; a1.transA = 0;
        a1.Bhi = A2hi; a1.Blo = A2lo; a1.sB = (long)E * Kd;
        a1.Chi = Hhi; a1.Clo = Hlo; a1.sHL = (long)E * Kd;
        a1.Ktot = E; a1.Mvalid = E;
        mma_gemm<true, false><<<dim3(12, 1, Bn), 256, SMEM_MMA_BYTES>>>(
            a0, a1, 6);
    }
    // L4: G5 sv = score(I@M1 + wvv) | G8 sq = score(T@H + wqq)
    {
        GArgs a0 = Z, a1 = Z;
        a0.Ahi = Ihi; a0.Alo = Ilo; a0.sA = (long)LV * E;
        a0.Bhi = M1hi; a0.Blo = M1lo; a0.sB = (long)E * Kd;
        a0.Uhi = wvvhi; a0.Ulo = wvvlo; a0.sU = (long)LV * Kd; a0.wh = whv;
        a0.Sout = sv; a0.sS = LV;
        a0.Ktot = E; a0.Mvalid = LV;
        a1.Ahi = Thi; a1.Alo = Tlo; a1.sA = (long)LT * E;
        a1.Bhi = Hhi; a1.Blo = Hlo; a1.sB = (long)E * Kd;
        a1.Uhi = wqqhi; a1.Ulo = wqqlo; a1.sU = (long)LT * Kd; a1.wh = whq;
        a1.Sout = sq; a1.sS = LT;
        a1.Ktot = E; a1.Mvalid = LT;
        mma_gemm<false, true><<<dim3(5 + 8, 1, Bn), 256, SMEM_MMA_BYTES>>>(
            a0, a1, 5);
    }

    // --- softmax (merged) / context partials / output ---
    softmax2_kernel<<<2 * Bn, 256>>>(sv, sq);
    context_part<<<dim3(Bn, NP), 768>>>(T, I, sq, sv, ctxp);
    out_kernel<<<Bn, 768>>>(ctxp, ws, out);
}

// round 11
// speedup vs baseline: 1.1923x; 1.0041x over previous
#include <cuda_runtime.h>
#include <cuda_bf16.h>
#include <math.h>
#include <stdint.h>

// Problem constants: B=64, LT=1024, LV=576, E=768, K=128
namespace cfg {
constexpr int Bn = 64;
constexpr int LT = 1024;
constexpr int LV = 576;
constexpr int E  = 768;
constexpr int Kd = 128;
constexpr int NP = 8;    // context partial slices
}
using bf16 = __nv_bfloat16;

__device__ __forceinline__ void split2(float v, bf16& h, bf16& l) {
    h = __float2bfloat16(v);
    l = __float2bfloat16(v - __bfloat162float(h));
}

__device__ __forceinline__ uint32_t pack_bf2(bf16 a, bf16 b) {
    union { bf16 h[2]; uint32_t u; } w;
    w.h[0] = a; w.h[1] = b;
    return w.u;
}

__device__ __forceinline__ void mma16816(float* d, const uint32_t* a, const uint32_t* b) {
    asm volatile(
        "mma.sync.aligned.m16n8k16.row.col.f32.bf16.bf16.f32 "
        "{%0,%1,%2,%3}, {%4,%5,%6,%7}, {%8,%9}, {%0,%1,%2,%3};"
        : "+f"(d[0]), "+f"(d[1]), "+f"(d[2]), "+f"(d[3])
        : "r"(a[0]), "r"(a[1]), "r"(a[2]), "r"(a[3]), "r"(b[0]), "r"(b[1]));
}

__device__ __forceinline__ void ldm_x4(uint32_t* r, uint32_t saddr) {
    asm volatile("ldmatrix.sync.aligned.m8n8.x4.shared.b16 {%0,%1,%2,%3}, [%4];"
        : "=r"(r[0]), "=r"(r[1]), "=r"(r[2]), "=r"(r[3]) : "r"(saddr));
}
__device__ __forceinline__ void ldm_x4t(uint32_t* r, uint32_t saddr) {
    asm volatile("ldmatrix.sync.aligned.m8n8.x4.trans.shared.b16 {%0,%1,%2,%3}, [%4];"
        : "=r"(r[0]), "=r"(r[1]), "=r"(r[2]), "=r"(r[3]) : "r"(saddr));
}

__device__ __forceinline__ uint32_t smem_u32(const void* p) {
    uint32_t a;
    asm("{ .reg .u64 t; cvta.to.shared.u64 t, %1; cvt.u32.u64 %0, t; }"
        : "=r"(a) : "l"(p));
    return a;
}

#define CP_ASYNC16(s, g) \
    asm volatile("cp.async.cg.shared.global [%0], [%1], 16;" :: "r"(s), "l"(g))
#define CP_COMMIT() asm volatile("cp.async.commit_group;")
#define CP_WAIT1()  asm volatile("cp.async.wait_group 1;")
#define CP_WAIT0()  asm volatile("cp.async.wait_group 0;")

#define SWZ64(row, kb)  ((uint32_t)((row) * 64  + ((kb) ^ (((row) & 3) << 4))))
#define SWZ256(row, kb) ((uint32_t)((row) * 256 + ((kb) ^ (((row) & 7) << 4))))

// ===========================================================================
// Scratch (device globals; zero-initialized)
// ===========================================================================
#define DEV_BF16(name, n) __device__ __align__(256) bf16 name[n]
DEV_BF16(g_Thi,  64 * 1024 * 768);
DEV_BF16(g_Tlo,  64 * 1024 * 768);
DEV_BF16(g_Ihi,  64 * 576 * 768 + 64 * 768);   // +pad: GEMM5 reads 64 extra rows
DEV_BF16(g_Ilo,  64 * 576 * 768 + 64 * 768);
DEV_BF16(g_wbhi,  768 * 768);
DEV_BF16(g_wblo,  768 * 768);
DEV_BF16(g_wqhi,  768 * 128);
DEV_BF16(g_wqlo,  768 * 128);
DEV_BF16(g_wvhi,  768 * 128);
DEV_BF16(g_wvlo,  768 * 128);
DEV_BF16(g_wqqhi, 64 * 1024 * 128);
DEV_BF16(g_wqqlo, 64 * 1024 * 128);
DEV_BF16(g_wvvhi, 64 * 576 * 128);
DEV_BF16(g_wvvlo, 64 * 576 * 128);
DEV_BF16(g_A1hi,  64 * 768 * 128);
DEV_BF16(g_A1lo,  64 * 768 * 128);
DEV_BF16(g_M1hi,  64 * 768 * 128);
DEV_BF16(g_M1lo,  64 * 768 * 128);
DEV_BF16(g_A2hi,  64 * 768 * 128);
DEV_BF16(g_A2lo,  64 * 768 * 128);
DEV_BF16(g_Hhi,   64 * 768 * 128);
DEV_BF16(g_Hlo,   64 * 768 * 128);

__device__ float g_sv  [cfg::Bn * cfg::LV];
__device__ float g_sq  [cfg::Bn * cfg::LT];
__device__ float g_ctxp[cfg::Bn * cfg::NP * cfg::E];

// ===========================================================================
// Flat conversion: fp32 -> bf16 hi/lo
// ===========================================================================
__global__ void conv_flat(const float* __restrict__ X,
                          bf16* __restrict__ hi, bf16* __restrict__ lo, long n4)
{
    long idx = (long)blockIdx.x * blockDim.x + threadIdx.x;
    if (idx >= n4) return;
    float4 v = ((const float4*)X)[idx];
    union { bf16 h[4]; uint2 u; } H, L;
    split2(v.x, H.h[0], L.h[0]);
    split2(v.y, H.h[1], L.h[1]);
    split2(v.z, H.h[2], L.h[2]);
    split2(v.w, H.h[3], L.h[3]);
    ((uint2*)hi)[idx] = H.u;
    ((uint2*)lo)[idx] = L.u;
}

// ===========================================================================
// Merged-pair HMMA batched GEMM: C[M,128] = op(A)[M,K] @ B[K,128]
// ===========================================================================
constexpr int MATB   = 8192;
constexpr int STAGEB = 4 * MATB;
static constexpr int SMEM_MMA_BYTES = 3 * STAGEB;   // 98304 B

struct GArgs {
    const bf16 *Ahi, *Alo, *Bhi, *Blo;
    long sA, sB, sHL, sU, sS;
    bf16 *Chi, *Clo;
    const bf16 *Uhi, *Ulo;
    const float* wh;
    float* Sout;
    int Ktot, Mvalid, transA;
};

template <bool OUTHL, bool OUTS>
__global__ void __launch_bounds__(256, 2) mma_gemm(GArgs a0, GArgs a1, int splitX)
{
    extern __shared__ __align__(16) bf16 sm[];
    __shared__ float s_wh[128];
    const uint32_t smb = smem_u32(sm);

    const GArgs& A = (blockIdx.x < (unsigned)splitX) ? a0 : a1;
    const int bx = (blockIdx.x < (unsigned)splitX) ? blockIdx.x
                                                   : blockIdx.x - splitX;

    const int tid  = threadIdx.x;
    const int lane = tid & 31;
    const int wid  = tid >> 5;
    const int wm   = wid & 1;
    const int wn   = wid >> 1;
    const int g    = lane >> 2;
    const int t    = lane & 3;

    const long z    = blockIdx.z;
    const int  m0   = bx * 128;
    const int  Ktot = A.Ktot;
    const bool trA  = (A.transA != 0);

    if (OUTS && tid < 128) s_wh[tid] = A.wh[tid];

    const bf16* Ah = A.Ahi + z * A.sA + (trA ? 0 : (long)m0 * 768);
    const bf16* Al = A.Alo + z * A.sA + (trA ? 0 : (long)m0 * 768);
    const bf16* Bh = A.Bhi + z * A.sB;
    const bf16* Bl = A.Blo + z * A.sB;

    float acc[4][4][4];
#pragma unroll
    for (int i = 0; i < 4; i++)
#pragma unroll
        for (int j = 0; j < 4; j++)
#pragma unroll
            for (int q = 0; q < 4; q++) acc[i][j][q] = 0.f;

    const int nch = Ktot >> 5;

    const int nrow0 = (tid * 2)     >> 2, nc0 = ((tid * 2)     & 3) * 16;
    const int nrow1 = (tid * 2 + 1) >> 2, nc1 = ((tid * 2 + 1) & 3) * 16;
    const int trow0 = (tid * 2)     >> 4, tc0 = ((tid * 2)     & 15) * 16;
    const int trow1 = (tid * 2 + 1) >> 4, tc1 = ((tid * 2 + 1) & 15) * 16;

    auto load_chunk = [&](int c, int stage) {
        const int k0 = c << 5;
        const uint32_t sb = smb + stage * STAGEB;
        if (trA) {
            CP_ASYNC16(sb + SWZ256(trow0, tc0),
                       Ah + (long)(k0 + trow0) * 768 + m0 + tc0 / 2);
            CP_ASYNC16(sb + SWZ256(trow1, tc1),
                       Ah + (long)(k0 + trow1) * 768 + m0 + tc1 / 2);
            CP_ASYNC16(sb + MATB + SWZ256(trow0, tc0),
                       Al + (long)(k0 + trow0) * 768 + m0 + tc0 / 2);
            CP_ASYNC16(sb + MATB + SWZ256(trow1, tc1),
                       Al + (long)(k0 + trow1) * 768 + m0 + tc1 / 2);
        } else {
            CP_ASYNC16(sb + SWZ64(nrow0, nc0),
                       Ah + (long)nrow0 * 768 + k0 + nc0 / 2);
            CP_ASYNC16(sb + SWZ64(nrow1, nc1),
                       Ah + (long)nrow1 * 768 + k0 + nc1 / 2);
            CP_ASYNC16(sb + MATB + SWZ64(nrow0, nc0),
                       Al + (long)nrow0 * 768 + k0 + nc0 / 2);
            CP_ASYNC16(sb + MATB + SWZ64(nrow1, nc1),
                       Al + (long)nrow1 * 768 + k0 + nc1 / 2);
        }
        CP_ASYNC16(sb + 2 * MATB + SWZ256(trow0, tc0),
                   Bh + (long)(k0 + trow0) * 128 + tc0 / 2);
        CP_ASYNC16(sb + 2 * MATB + SWZ256(trow1, tc1),
                   Bh + (long)(k0 + trow1) * 128 + tc1 / 2);
        CP_ASYNC16(sb + 3 * MATB + SWZ256(trow0, tc0),
                   Bl + (long)(k0 + trow0) * 128 + tc0 / 2);
        CP_ASYNC16(sb + 3 * MATB + SWZ256(trow1, tc1),
                   Bl + (long)(k0 + trow1) * 128 + tc1 / 2);
    };

    const int tr_r = lane & 7, tr_q = lane >> 3;
    const int klB = (tr_q & 1) * 8 + tr_r;
    const int nbB = (tr_q >> 1) * 16;
    const int klA = (tr_q >> 1) * 8 + tr_r;
    const int mbA = (tr_q & 1) * 16;
    const int aRow = (lane & 7) + ((lane >> 3) & 1) * 8;
    const int aKB  = (lane >> 4) * 16;

    auto compute_chunk = [&](int stage) {
        const uint32_t sb  = smb + stage * STAGEB;
        const uint32_t tAh = sb;
        const uint32_t tAl = sb + MATB;
        const uint32_t tBh = sb + 2 * MATB;
        const uint32_t tBl = sb + 3 * MATB;
#pragma unroll
        for (int ks = 0; ks < 2; ks++) {
            uint32_t bh[4][2], bl[4][2];
#pragma unroll
            for (int nfb = 0; nfb < 4; nfb += 2) {
                const int kr = ks * 16 + klB;
                const int nb = (wn * 32 + nfb * 8) * 2 + nbB;
                uint32_t r[4];
                ldm_x4t(r, tBh + SWZ256(kr, nb));
                bh[nfb][0] = r[0]; bh[nfb][1] = r[1];
                bh[nfb + 1][0] = r[2]; bh[nfb + 1][1] = r[3];
                ldm_x4t(r, tBl + SWZ256(kr, nb));
                bl[nfb][0] = r[0]; bl[nfb][1] = r[1];
                bl[nfb + 1][0] = r[2]; bl[nfb + 1][1] = r[3];
            }
#pragma unroll
            for (int mf = 0; mf < 4; mf++) {
                uint32_t ah[4], al[4];
                if (trA) {
                    const int kr = ks * 16 + klA;
                    const int mb = (wm * 64 + mf * 16) * 2 + mbA;
                    ldm_x4t(ah, tAh + SWZ256(kr, mb));
                    ldm_x4t(al, tAl + SWZ256(kr, mb));
                } else {
                    const int rr = wm * 64 + mf * 16 + aRow;
                    const int kb = ks * 32 + aKB;
                    ldm_x4(ah, tAh + SWZ64(rr, kb));
                    ldm_x4(al, tAl + SWZ64(rr, kb));
                }
                // interleaved grouping (round-8 ordering; measured faster)
#pragma unroll
                for (int nf = 0; nf < 4; nf++) {
                    mma16816(acc[mf][nf], ah, bh[nf]);
                    mma16816(acc[mf][nf], ah, bl[nf]);
                    mma16816(acc[mf][nf], al, bh[nf]);
                }
            }
        }
    };

    load_chunk(0, 0);
    CP_COMMIT();
    load_chunk(1, 1);
    CP_COMMIT();
    for (int c = 0; c < nch; c++) {
        if (c + 1 < nch) CP_WAIT1(); else CP_WAIT0();
        __syncthreads();
        if (c + 2 < nch) {
            load_chunk(c + 2, (c + 2) % 3);
            CP_COMMIT();
        }
        compute_chunk(c % 3);
    }

    // ---- epilogues ----
    if (OUTHL) {
#pragma unroll
        for (int mf = 0; mf < 4; mf++) {
#pragma unroll
            for (int nf = 0; nf < 4; nf++) {
                const int mr0 = m0 + wm * 64 + mf * 16 + g;
                const int mr1 = mr0 + 8;
                const int n0  = wn * 32 + nf * 8 + 2 * t;
                const float* cc = acc[mf][nf];
                bf16 h0, l0, h1, l1, h2, l2, h3, l3;
                split2(cc[0], h0, l0); split2(cc[1], h1, l1);
                split2(cc[2], h2, l2); split2(cc[3], h3, l3);
                if (mr0 < A.Mvalid) {
                    *(uint32_t*)(A.Chi + z * A.sHL + (long)mr0 * 128 + n0) =
                        pack_bf2(h0, h1);
                    *(uint32_t*)(A.Clo + z * A.sHL + (long)mr0 * 128 + n0) =
                        pack_bf2(l0, l1);
                }
                if (mr1 < A.Mvalid) {
                    *(uint32_t*)(A.Chi + z * A.sHL + (long)mr1 * 128 + n0) =
                        pack_bf2(h2, h3);
                    *(uint32_t*)(A.Clo + z * A.sHL + (long)mr1 * 128 + n0) =
                        pack_bf2(l2, l3);
                }
            }
        }
    }

    if (OUTS) {
        __syncthreads();                    // smem stages dead -> reuse
        float* part = (float*)sm;           // [4][128]
#pragma unroll
        for (int mf = 0; mf < 4; mf++) {
#pragma unroll
            for (int half = 0; half < 2; half++) {
                const int ml = wm * 64 + mf * 16 + half * 8 + g;
                const int mr = m0 + ml;
                float val = 0.f;
                if (mr < A.Mvalid) {
                    const bf16* uh = A.Uhi + z * A.sU + (long)mr * 128;
                    const bf16* ul = A.Ulo + z * A.sU + (long)mr * 128;
#pragma unroll
                    for (int nf = 0; nf < 4; nf++) {
                        const int n = wn * 32 + nf * 8 + 2 * t;
                        union { uint32_t u; bf16 h[2]; } H, L;
                        H.u = *(const uint32_t*)(uh + n);
                        L.u = *(const uint32_t*)(ul + n);
                        float u0 = __bfloat162float(H.h[0]) + __bfloat162float(L.h[0]);
                        float u1 = __bfloat162float(H.h[1]) + __bfloat162float(L.h[1]);
                        val += tanhf(u0 + acc[mf][nf][half * 2 + 0]) * s_wh[n];
                        val += tanhf(u1 + acc[mf][nf][half * 2 + 1]) * s_wh[n + 1];
                    }
                }
                val += __shfl_xor_sync(0xffffffffu, val, 1);
                val += __shfl_xor_sync(0xffffffffu, val, 2);
                if (t == 0) part[wn * 128 + ml] = val;
            }
        }
        __syncthreads();
        if (tid < 128) {
            const int mr = m0 + tid;
            if (mr < A.Mvalid) {
                float s = part[tid] + part[128 + tid] + part[256 + tid] + part[384 + tid];
                A.Sout[z * A.sS + mr] = s;
            }
        }
    }
}

// ===========================================================================
// Tail kernels
// ===========================================================================
// both softmaxes in one launch: blocks 0..63 -> sv (L=576), 64..127 -> sq (L=1024)
__global__ void softmax2_kernel(float* __restrict__ svp, float* __restrict__ sqp)
{
    const bool isv = blockIdx.x < cfg::Bn;
    const int  b   = isv ? blockIdx.x : blockIdx.x - cfg::Bn;
    const int  L   = isv ? cfg::LV : cfg::LT;
    float* row = (isv ? svp : sqp) + (long)b * L;

    __shared__ float red[32];
    __shared__ float bval;
    const int tid  = threadIdx.x;
    const int lane = tid & 31;
    const int wid  = tid >> 5;
    const int nw   = blockDim.x >> 5;

    float m = -1e30f;
    for (int i = tid; i < L; i += blockDim.x) m = fmaxf(m, row[i]);
#pragma unroll
    for (int o = 16; o > 0; o >>= 1) m = fmaxf(m, __shfl_xor_sync(0xffffffffu, m, o));
    if (lane == 0) red[wid] = m;
    __syncthreads();
    if (tid == 0) {
        float mm = red[0];
        for (int w = 1; w < nw; w++) mm = fmaxf(mm, red[w]);
        bval = mm;
    }
    __syncthreads();
    m = bval;
    __syncthreads();

    float sum = 0.f;
    for (int i = tid; i < L; i += blockDim.x) {
        float e = expf(row[i] - m);
        row[i] = e;
        sum += e;
    }
#pragma unroll
    for (int o = 16; o > 0; o >>= 1) sum += __shfl_xor_sync(0xffffffffu, sum, o);
    if (lane == 0) red[wid] = sum;
    __syncthreads();
    if (tid == 0) {
        float ss = 0.f;
        for (int w = 0; w < nw; w++) ss += red[w];
        bval = ss;
    }
    __syncthreads();
    float inv = 1.f / bval;
    for (int i = tid; i < L; i += blockDim.x) row[i] *= inv;
}

// partial context: grid (Bn, NP); slice p covers LV/NP image rows + LT/NP text rows
__global__ void __launch_bounds__(768) context_part(
    const float* __restrict__ T, const float* __restrict__ I,
    const float* __restrict__ aq, const float* __restrict__ av,
    float* __restrict__ ctxp)
{
    constexpr int YS = cfg::LV / cfg::NP;   // 72
    constexpr int XS = cfg::LT / cfg::NP;   // 128
    __shared__ float sq[XS];
    __shared__ float sv[YS];
    const int b = blockIdx.x;
    const int p = blockIdx.y;
    const int d = threadIdx.x;
    if (d < XS) sq[d] = aq[(long)b * cfg::LT + p * XS + d];
    if (d < YS) sv[d] = av[(long)b * cfg::LV + p * YS + d];
    __syncthreads();

    const float* Ib = I + (long)b * cfg::LV * cfg::E + (long)(p * YS) * cfg::E + d;
    const float* Tb = T + (long)b * cfg::LT * cfg::E + (long)(p * XS) * cfg::E + d;
    float acc = 0.f;
#pragma unroll 4
    for (int y = 0; y < YS; y++) acc += sv[y] * Ib[(long)y * cfg::E];
#pragma unroll 4
    for (int x = 0; x < XS; x++) acc += sq[x] * Tb[(long)x * cfg::E];
    ctxp[((long)b * cfg::NP + p) * cfg::E + d] = acc;
}

__global__ void __launch_bounds__(768) out_kernel(
    const float* __restrict__ ctxp, const float* __restrict__ ws,
    float* __restrict__ out)
{
    __shared__ float sc[cfg::E];
    const int b = blockIdx.x;
    const int e = threadIdx.x;
    float c = 0.f;
#pragma unroll
    for (int p = 0; p < cfg::NP; p++)
        c += ctxp[((long)b * cfg::NP + p) * cfg::E + e];
    sc[e] = c;
    __syncthreads();
    float acc = 0.f;
#pragma unroll 8
    for (int d = 0; d < cfg::E; d++)
        acc += sc[d] * ws[(long)d * cfg::E + e];
    out[(long)b * cfg::E + e] = tanhf(acc);
}

// ===========================================================================
// launch
// ===========================================================================
extern "C" void kernel_launch(void* const* d_in, const int* in_sizes, int n_in,
                              void* d_out, int out_size)
{
    using namespace cfg;
    const float* T   = (const float*)d_in[0];
    const float* I   = (const float*)d_in[1];
    const float* wb  = (const float*)d_in[3];
    const float* wv  = (const float*)d_in[4];
    const float* wq  = (const float*)d_in[5];
    const float* whv = (const float*)d_in[6];
    const float* whq = (const float*)d_in[7];
    const float* ws  = (const float*)d_in[8];
    float* out = (float*)d_out;

    bf16 *Thi, *Tlo, *Ihi, *Ilo, *wbhi, *wblo, *wqhi, *wqlo, *wvhi, *wvlo;
    bf16 *wqqhi, *wqqlo, *wvvhi, *wvvlo;
    bf16 *A1hi, *A1lo, *M1hi, *M1lo, *A2hi, *A2lo, *Hhi, *Hlo;
    float *sv, *sq, *ctxp;

    cudaGetSymbolAddress((void**)&Thi, g_Thi);   cudaGetSymbolAddress((void**)&Tlo, g_Tlo);
    cudaGetSymbolAddress((void**)&Ihi, g_Ihi);   cudaGetSymbolAddress((void**)&Ilo, g_Ilo);
    cudaGetSymbolAddress((void**)&wbhi, g_wbhi); cudaGetSymbolAddress((void**)&wblo, g_wblo);
    cudaGetSymbolAddress((void**)&wqhi, g_wqhi); cudaGetSymbolAddress((void**)&wqlo, g_wqlo);
    cudaGetSymbolAddress((void**)&wvhi, g_wvhi); cudaGetSymbolAddress((void**)&wvlo, g_wvlo);
    cudaGetSymbolAddress((void**)&wqqhi, g_wqqhi); cudaGetSymbolAddress((void**)&wqqlo, g_wqqlo);
    cudaGetSymbolAddress((void**)&wvvhi, g_wvvhi); cudaGetSymbolAddress((void**)&wvvlo, g_wvvlo);
    cudaGetSymbolAddress((void**)&A1hi, g_A1hi); cudaGetSymbolAddress((void**)&A1lo, g_A1lo);
    cudaGetSymbolAddress((void**)&M1hi, g_M1hi); cudaGetSymbolAddress((void**)&M1lo, g_M1lo);
    cudaGetSymbolAddress((void**)&A2hi, g_A2hi); cudaGetSymbolAddress((void**)&A2lo, g_A2lo);
    cudaGetSymbolAddress((void**)&Hhi, g_Hhi);   cudaGetSymbolAddress((void**)&Hlo, g_Hlo);
    cudaGetSymbolAddress((void**)&sv, g_sv);     cudaGetSymbolAddress((void**)&sq, g_sq);
    cudaGetSymbolAddress((void**)&ctxp, g_ctxp);

    cudaFuncSetAttribute(mma_gemm<true, false>,
        cudaFuncAttributeMaxDynamicSharedMemorySize, SMEM_MMA_BYTES);
    cudaFuncSetAttribute(mma_gemm<false, true>,
        cudaFuncAttributeMaxDynamicSharedMemorySize, SMEM_MMA_BYTES);

    // --- conversions ---
    {
        long nT = (long)Bn * LT * E / 4, nI = (long)Bn * LV * E / 4;
        long nWb = (long)E * E / 4, nW = (long)E * Kd / 4;
        conv_flat<<<(unsigned)((nT + 255) / 256), 256>>>(T, Thi, Tlo, nT);
        conv_flat<<<(unsigned)((nI + 255) / 256), 256>>>(I, Ihi, Ilo, nI);
        conv_flat<<<(unsigned)((nWb + 255) / 256), 256>>>(wb, wbhi, wblo, nWb);
        conv_flat<<<(unsigned)((nW + 255) / 256), 256>>>(wq, wqhi, wqlo, nW);
        conv_flat<<<(unsigned)((nW + 255) / 256), 256>>>(wv, wvhi, wvlo, nW);
    }

    GArgs Z{};

    // L1: G1 wqq = T@wq | G2 wvv = I@wv
    {
        GArgs a0 = Z, a1 = Z;
        a0.Ahi = Thi; a0.Alo = Tlo; a0.Bhi = wqhi; a0.Blo = wqlo;
        a0.Chi = wqqhi; a0.Clo = wqqlo;
        a0.Ktot = E; a0.Mvalid = Bn * LT;
        a1.Ahi = Ihi; a1.Alo = Ilo; a1.Bhi = wvhi; a1.Blo = wvlo;
        a1.Chi = wvvhi; a1.Clo = wvvlo;
        a1.Ktot = E; a1.Mvalid = Bn * LV;
        mma_gemm<true, false><<<dim3(512 + 288, 1, 1), 256, SMEM_MMA_BYTES>>>(
            a0, a1, 512);
    }
    // L2: G3 A1 = T^T@wqq (transA, K=1024) | G6 A2 = I^T@wvv (transA, K=576)
    {
        GArgs a0 = Z, a1 = Z;
        a0.Ahi = Thi; a0.Alo = Tlo; a0.sA = (long)LT * E; a0.transA = 1;
        a0.Bhi = wqqhi; a0.Blo = wqqlo; a0.sB = (long)LT * Kd;
        a0.Chi = A1hi; a0.Clo = A1lo; a0.sHL = (long)E * Kd;
        a0.Ktot = LT; a0.Mvalid = E;
        a1.Ahi = Ihi; a1.Alo = Ilo; a1.sA = (long)LV * E; a1.transA = 1;
        a1.Bhi = wvvhi; a1.Blo = wvvlo; a1.sB = (long)LV * Kd;
        a1.Chi = A2hi; a1.Clo = A2lo; a1.sHL = (long)E * Kd;
        a1.Ktot = LV; a1.Mvalid = E;
        mma_gemm<true, false><<<dim3(12, 1, Bn), 256, SMEM_MMA_BYTES>>>(
            a0, a1, 6);
    }
    // L3: G4 M1 = wb^T@A1 (transA) | G7 H = wb@A2 (normal A)
    {
        GArgs a0 = Z, a1 = Z;
        a0.Ahi = wbhi; a0.Alo = wblo; a0.transA = 1;
        a0.Bhi = A1hi; a0.Blo = A1lo; a0.sB = (long)E * Kd;
        a0.Chi = M1hi; a0.Clo = M1lo; a0.sHL = (long)E * Kd;
        a0.Ktot = E; a0.Mvalid = E;
        a1.Ahi = wbhi; a1.Alo = wblo; a1.transA = 0;
        a1.Bhi = A2hi; a1.Blo = A2lo; a1.sB = (long)E * Kd;
        a1.Chi = Hhi; a1.Clo = Hlo; a1.sHL = (long)E * Kd;
        a1.Ktot = E; a1.Mvalid = E;
        mma_gemm<true, false><<<dim3(12, 1, Bn), 256, SMEM_MMA_BYTES>>>(
            a0, a1, 6);
    }
    // L4: G5 sv = score(I@M1 + wvv) | G8 sq = score(T@H + wqq)
    {
        GArgs a0 = Z, a1 = Z;
        a0.Ahi = Ihi; a0.Alo = Ilo; a0.sA = (long)LV * E;
        a0.Bhi = M1hi; a0.Blo = M1lo; a0.sB = (long)E * Kd;
        a0.Uhi = wvvhi; a0.Ulo = wvvlo; a0.sU = (long)LV * Kd; a0.wh = whv;
        a0.Sout = sv; a0.sS = LV;
        a0.Ktot = E; a0.Mvalid = LV;
        a1.Ahi = Thi; a1.Alo = Tlo; a1.sA = (long)LT * E;
        a1.Bhi = Hhi; a1.Blo = Hlo; a1.sB = (long)E * Kd;
        a1.Uhi = wqqhi; a1.Ulo = wqqlo; a1.sU = (long)LT * Kd; a1.wh = whq;
        a1.Sout = sq; a1.sS = LT;
        a1.Ktot = E; a1.Mvalid = LT;
        mma_gemm<false, true><<<dim3(5 + 8, 1, Bn), 256, SMEM_MMA_BYTES>>>(
            a0, a1, 5);
    }

    // --- softmax (merged) / context partials / output ---
    softmax2_kernel<<<2 * Bn, 256>>>(sv, sq);
    context_part<<<dim3(Bn, NP), 768>>>(T, I, sq, sv, ctxp);
    out_kernel<<<Bn, 768>>>(ctxp, ws, out);
}